// round 16
// baseline (speedup 1.0000x reference)
#include <cuda_runtime.h>
#include <cuda_fp16.h>
#include <math.h>

// Problem constants
#define BB 2
#define SS 2048
#define HID 2048
#define NH 16
#define NKVH 2
#define DH 256
#define ROT 64
#define MM (BB*SS)          // 4096 tokens
#define QGN (NH*DH*2)       // 8192
#define KVN (NKVH*DH)       // 512
#define ODIM (NH*DH)        // 4096

// Scratch (device globals)
__device__ __half g_hs  [(size_t)MM * HID];
__device__ __half g_wqt [(size_t)QGN * HID];
__device__ __half g_wkvt[(size_t)(2*KVN) * HID];     // [Wk^T ; Wv^T]
__device__ __half g_wot [(size_t)HID * ODIM];
__device__ __half g_qg  [(size_t)MM * QGN];          // fp16 (q | gate)
__device__ __half g_kv  [(size_t)MM * KVN];          // fp16, K only
__device__ __half g_kr  [(size_t)BB * NKVH * SS * DH];
__device__ __half g_vr  [(size_t)KVN * MM];          // [kvh*256+d][b*2048+s]
__device__ __half g_attn[(size_t)MM * ODIM];

// ---------------- device helpers ----------------
__device__ __forceinline__ unsigned smem_u32(const void* p) {
    unsigned a;
    asm("{ .reg .u64 t; cvta.to.shared.u64 t, %1; cvt.u32.u64 %0, t; }" : "=r"(a) : "l"(p));
    return a;
}
__device__ __forceinline__ void mma_f16(float c[4], const unsigned a[4], const unsigned* b) {
    asm volatile(
        "mma.sync.aligned.m16n8k16.row.col.f32.f16.f16.f32 "
        "{%0,%1,%2,%3}, {%4,%5,%6,%7}, {%8,%9}, {%0,%1,%2,%3};\n"
        : "+f"(c[0]), "+f"(c[1]), "+f"(c[2]), "+f"(c[3])
        : "r"(a[0]), "r"(a[1]), "r"(a[2]), "r"(a[3]), "r"(b[0]), "r"(b[1]));
}
__device__ __forceinline__ void ldsm4(unsigned r[4], const __half* p) {
    unsigned a = smem_u32(p);
    asm volatile("ldmatrix.sync.aligned.m8n8.x4.shared.b16 {%0,%1,%2,%3}, [%4];\n"
                 : "=r"(r[0]), "=r"(r[1]), "=r"(r[2]), "=r"(r[3]) : "r"(a));
}
__device__ __forceinline__ void cp16(void* dst, const void* src) {
    unsigned d = (unsigned)__cvta_generic_to_shared(dst);
    asm volatile("cp.async.cg.shared.global [%0], [%1], 16;\n" :: "r"(d), "l"(src));
}
__device__ __forceinline__ void cp_commit() { asm volatile("cp.async.commit_group;\n"); }
__device__ __forceinline__ unsigned pack_h2(float a, float b) {
    __half2 h = __floats2half2_rn(a, b);
    return *(unsigned*)&h;
}

// ---------------------------------------------------------------------------
// Merged prep kernel (round-15)
// ---------------------------------------------------------------------------
#define NB_HS 1024
#define NB_WQ ((QGN/32)*(HID/32))   // 16384
#define NB_WK ((KVN/32)*(HID/32))   // 1024
#define NB_WO ((HID/32)*(ODIM/32))  // 8192
#define NB_PREP (NB_HS + NB_WQ + 2*NB_WK + NB_WO)

__device__ __forceinline__ void tr_tile(
    float (*t)[33], const float* __restrict__ src, __half* __restrict__ dst,
    int R, int C, int bx, int by, int tid)
{
    const int tx = tid & 31, ty = tid >> 5;
    const int x = bx * 32 + tx;
    const int y0 = by * 32;
#pragma unroll
    for (int i = 0; i < 4; i++)
        t[ty + i * 8][tx] = src[(size_t)(y0 + ty + i * 8) * C + x];
    __syncthreads();
    const int nx = by * 32 + tx;
    const int ny0 = bx * 32;
#pragma unroll
    for (int i = 0; i < 4; i++)
        dst[(size_t)(ny0 + ty + i * 8) * R + nx] = __float2half(t[tx][ty + i * 8]);
}

__global__ __launch_bounds__(256) void prep_kernel(
    const float* __restrict__ hs,
    const float* __restrict__ Wq, const float* __restrict__ Wk,
    const float* __restrict__ Wv, const float* __restrict__ Wo)
{
    __shared__ float t[32][33];
    const int tid = threadIdx.x;
    int id = blockIdx.x;

    if (id < NB_HS) {
        const int n8 = MM * HID / 8;
        for (int i = id * 256 + tid; i < n8; i += NB_HS * 256) {
            float4 v0 = ((const float4*)hs)[i * 2];
            float4 v1 = ((const float4*)hs)[i * 2 + 1];
            __half2 h[4];
            h[0] = __floats2half2_rn(v0.x, v0.y);
            h[1] = __floats2half2_rn(v0.z, v0.w);
            h[2] = __floats2half2_rn(v1.x, v1.y);
            h[3] = __floats2half2_rn(v1.z, v1.w);
            ((uint4*)g_hs)[i] = *(uint4*)h;
        }
        return;
    }
    id -= NB_HS;
    if (id < NB_WQ) { tr_tile(t, Wq, g_wqt, HID, QGN, id % (QGN/32), id / (QGN/32), tid); return; }
    id -= NB_WQ;
    if (id < NB_WK) { tr_tile(t, Wk, g_wkvt, HID, KVN, id % (KVN/32), id / (KVN/32), tid); return; }
    id -= NB_WK;
    if (id < NB_WK) { tr_tile(t, Wv, g_wkvt + (size_t)KVN * HID, HID, KVN, id % (KVN/32), id / (KVN/32), tid); return; }
    id -= NB_WK;
    tr_tile(t, Wo, g_wot, ODIM, HID, id % (HID/32), id / (HID/32), tid);
}

// ---------------------------------------------------------------------------
// fp16 GEMM config: CTA 128x128, BK=32, 3-stage, 8 warps (4x2), warp 32x64.
// ---------------------------------------------------------------------------
#define GS_STR 40
#define TG_SMEM ((3*128*GS_STR + 3*128*GS_STR) * (int)sizeof(__half))

__global__ __launch_bounds__(256, 2) void hgemm_qkv_kernel()
{
    extern __shared__ __half hsm[];
    __half* As = hsm;
    __half* Bs = hsm + 3 * 128 * GS_STR;

    const int tid = threadIdx.x;
    int cid = blockIdx.x;
    const __half *A, *Bt; __half* C; int N, bx, by;
    if (cid < 2048)      { A = g_hs; Bt = g_wqt; C = g_qg; N = QGN; bx = cid & 63; by = cid >> 6; }
    else if (cid < 2176) { cid -= 2048; A = g_hs; Bt = g_wkvt; C = g_kv; N = KVN; bx = cid & 3; by = cid >> 2; }
    else                 { cid -= 2176; A = g_wkvt + (size_t)KVN * HID; Bt = g_hs; C = g_vr; N = MM; bx = cid & 31; by = cid >> 5; }

    const int lane = tid & 31;
    const int g = lane >> 2, t = lane & 3;
    const int wid = tid >> 5;
    const int m0 = (wid >> 1) * 32;
    const int n0 = (wid & 1) * 64;

    const int a_row = ((lane >> 3) & 1) * 8 + (lane & 7);
    const int a_kh  = (lane >> 4) * 8;
    const int b_row = ((lane >> 4) & 1) * 8 + (lane & 7);
    const int b_kh  = ((lane >> 3) & 1) * 8;

    const int nk = HID >> 5;

    auto issue = [&](int st, int k0) {
        __half* Ad = As + (size_t)st * 128 * GS_STR;
        __half* Bd = Bs + (size_t)st * 128 * GS_STR;
#pragma unroll
        for (int it = 0; it < 2; it++) {
            int idx = tid + it * 256;
            int row = idx >> 2;
            int ch  = (idx & 3) * 8;
            cp16(Ad + row * GS_STR + ch, A + (size_t)(by * 128 + row) * HID + k0 + ch);
            cp16(Bd + row * GS_STR + ch, Bt + (size_t)(bx * 128 + row) * HID + k0 + ch);
        }
        cp_commit();
    };

    issue(0, 0); issue(1, 32); issue(2, 64);

    float acc[2][8][4];
#pragma unroll
    for (int mt = 0; mt < 2; mt++)
#pragma unroll
        for (int nt = 0; nt < 8; nt++)
#pragma unroll
            for (int r = 0; r < 4; r++) acc[mt][nt][r] = 0.f;

    for (int i = 0; i < nk; i++) {
        const int st = i % 3;
        __half* Ad = As + (size_t)st * 128 * GS_STR;
        __half* Bd = Bs + (size_t)st * 128 * GS_STR;
        if (i + 2 < nk)      asm volatile("cp.async.wait_group 2;\n");
        else if (i + 1 < nk) asm volatile("cp.async.wait_group 1;\n");
        else                 asm volatile("cp.async.wait_group 0;\n");
        __syncthreads();

#pragma unroll
        for (int kk = 0; kk < 32; kk += 16) {
            unsigned a[2][4], bfr[4][4];
#pragma unroll
            for (int mt = 0; mt < 2; mt++)
                ldsm4(a[mt], Ad + (m0 + mt * 16 + a_row) * GS_STR + kk + a_kh);
#pragma unroll
            for (int p = 0; p < 4; p++)
                ldsm4(bfr[p], Bd + (n0 + p * 16 + b_row) * GS_STR + kk + b_kh);
#pragma unroll
            for (int mt = 0; mt < 2; mt++)
#pragma unroll
                for (int nt = 0; nt < 8; nt++)
                    mma_f16(acc[mt][nt], a[mt], &bfr[nt >> 1][(nt & 1) * 2]);
        }
        __syncthreads();
        if (i + 3 < nk) issue(st, (i + 3) * 32);
    }

#pragma unroll
    for (int mt = 0; mt < 2; mt++) {
        const int r = by * 128 + m0 + mt * 16 + g;
#pragma unroll
        for (int nt = 0; nt < 8; nt++) {
            const int c = bx * 128 + n0 + nt * 8 + 2 * t;
            *(__half2*)(C + (size_t)r * N + c) =
                __floats2half2_rn(acc[mt][nt][0], acc[mt][nt][1]);
            *(__half2*)(C + (size_t)(r + 8) * N + c) =
                __floats2half2_rn(acc[mt][nt][2], acc[mt][nt][3]);
        }
    }
}

__global__ __launch_bounds__(256, 2) void hgemm_o_kernel(float* __restrict__ out)
{
    extern __shared__ __half hsm[];
    __half* As = hsm;
    __half* Bs = hsm + 3 * 128 * GS_STR;

    const int tid = threadIdx.x;
    const int bx = blockIdx.x, by = blockIdx.y;
    const __half* A  = g_attn;
    const __half* Bt = g_wot;
    const int N = HID;

    const int lane = tid & 31;
    const int g = lane >> 2, t = lane & 3;
    const int wid = tid >> 5;
    const int m0 = (wid >> 1) * 32;
    const int n0 = (wid & 1) * 64;

    const int a_row = ((lane >> 3) & 1) * 8 + (lane & 7);
    const int a_kh  = (lane >> 4) * 8;
    const int b_row = ((lane >> 4) & 1) * 8 + (lane & 7);
    const int b_kh  = ((lane >> 3) & 1) * 8;

    const int nk = ODIM >> 5;

    auto issue = [&](int st, int k0) {
        __half* Ad = As + (size_t)st * 128 * GS_STR;
        __half* Bd = Bs + (size_t)st * 128 * GS_STR;
#pragma unroll
        for (int it = 0; it < 2; it++) {
            int idx = tid + it * 256;
            int row = idx >> 2;
            int ch  = (idx & 3) * 8;
            cp16(Ad + row * GS_STR + ch, A + (size_t)(by * 128 + row) * ODIM + k0 + ch);
            cp16(Bd + row * GS_STR + ch, Bt + (size_t)(bx * 128 + row) * ODIM + k0 + ch);
        }
        cp_commit();
    };

    issue(0, 0); issue(1, 32); issue(2, 64);

    float acc[2][8][4];
#pragma unroll
    for (int mt = 0; mt < 2; mt++)
#pragma unroll
        for (int nt = 0; nt < 8; nt++)
#pragma unroll
            for (int r = 0; r < 4; r++) acc[mt][nt][r] = 0.f;

    for (int i = 0; i < nk; i++) {
        const int st = i % 3;
        __half* Ad = As + (size_t)st * 128 * GS_STR;
        __half* Bd = Bs + (size_t)st * 128 * GS_STR;
        if (i + 2 < nk)      asm volatile("cp.async.wait_group 2;\n");
        else if (i + 1 < nk) asm volatile("cp.async.wait_group 1;\n");
        else                 asm volatile("cp.async.wait_group 0;\n");
        __syncthreads();

#pragma unroll
        for (int kk = 0; kk < 32; kk += 16) {
            unsigned a[2][4], bfr[4][4];
#pragma unroll
            for (int mt = 0; mt < 2; mt++)
                ldsm4(a[mt], Ad + (m0 + mt * 16 + a_row) * GS_STR + kk + a_kh);
#pragma unroll
            for (int p = 0; p < 4; p++)
                ldsm4(bfr[p], Bd + (n0 + p * 16 + b_row) * GS_STR + kk + b_kh);
#pragma unroll
            for (int mt = 0; mt < 2; mt++)
#pragma unroll
                for (int nt = 0; nt < 8; nt++)
                    mma_f16(acc[mt][nt], a[mt], &bfr[nt >> 1][(nt & 1) * 2]);
        }
        __syncthreads();
        if (i + 3 < nk) issue(st, (i + 3) * 32);
    }

#pragma unroll
    for (int mt = 0; mt < 2; mt++) {
        const int r = by * 128 + m0 + mt * 16 + g;
#pragma unroll
        for (int nt = 0; nt < 8; nt++) {
            const int c = bx * 128 + n0 + nt * 8 + 2 * t;
            *(float2*)(out + (size_t)r * N + c)       = make_float2(acc[mt][nt][0], acc[mt][nt][1]);
            *(float2*)(out + (size_t)(r + 8) * N + c) = make_float2(acc[mt][nt][2], acc[mt][nt][3]);
        }
    }
}

// ---------------------------------------------------------------------------
// Post-process: K ONLY now (2 units/token), one warp per (token, kvh).
// ---------------------------------------------------------------------------
__global__ __launch_bounds__(256) void k_post_kernel(
    const float* __restrict__ cosp, const float* __restrict__ sinp,
    const float* __restrict__ kw)
{
    const int wi = blockIdx.x * 8 + (threadIdx.x >> 5);
    const int lane = threadIdx.x & 31;
    const int token = wi >> 1;
    const int unit  = wi & 1;
    const int b = token >> 11;
    const int s = token & 2047;
    const int d0 = lane * 8;

    const __half* src = g_kv + (size_t)token * KVN + unit * 256 + d0;
    uint4 raw = *(const uint4*)src;
    const __half* hx = (const __half*)&raw;
    float x[8];
#pragma unroll
    for (int j = 0; j < 8; j++) x[j] = __half2float(hx[j]);

    float ss = 0.f;
#pragma unroll
    for (int j = 0; j < 8; j++) ss += x[j] * x[j];
#pragma unroll
    for (int o = 16; o; o >>= 1) ss += __shfl_xor_sync(0xffffffffu, ss, o);
    const float rsn = rsqrtf(ss * (1.0f / 256.0f) + 1e-6f);

    float xn[8];
#pragma unroll
    for (int j = 0; j < 8; j++) xn[j] = x[j] * rsn * (1.0f + kw[d0 + j]);

    float rot[8];
#pragma unroll
    for (int j = 0; j < 8; j++) rot[j] = __shfl_xor_sync(0xffffffffu, xn[j], 4);
    if (lane < 8) {
        float cs[8], sn[8];
        *(float4*)(cs)     = *(const float4*)(cosp + (size_t)token * ROT + d0);
        *(float4*)(cs + 4) = *(const float4*)(cosp + (size_t)token * ROT + d0 + 4);
        *(float4*)(sn)     = *(const float4*)(sinp + (size_t)token * ROT + d0);
        *(float4*)(sn + 4) = *(const float4*)(sinp + (size_t)token * ROT + d0 + 4);
#pragma unroll
        for (int j = 0; j < 8; j++) {
            float rr = (lane & 4) ? rot[j] : -rot[j];
            xn[j] = xn[j] * cs[j] + rr * sn[j];
        }
    }

    __half2 h[4];
#pragma unroll
    for (int j = 0; j < 4; j++) h[j] = __floats2half2_rn(xn[2*j], xn[2*j+1]);
    *(uint4*)(g_kr + (((size_t)b * NKVH + unit) * SS + s) * DH + d0) = *(uint4*)h;
}

// ---------------------------------------------------------------------------
// Flash attention v9: inline Q RMSNorm+RoPE (per-warp private), warp-
// autonomous, register-resident P, K+V double-buffered, rescale-skip vote,
// heavy q-tiles first, masked-warp skip.
// ---------------------------------------------------------------------------
#define QS_STR 264
#define KS_STR 264
#define VS_STR 72
#define FL_SMEM ((128*QS_STR + 2*64*KS_STR + 2*256*VS_STR) * 2)

__global__ __launch_bounds__(256, 1) void flash_kernel(
    const float* __restrict__ cosp, const float* __restrict__ sinp,
    const float* __restrict__ qw)
{
    extern __shared__ __half smh[];
    __half* Qs = smh;                        // [128][QS_STR]
    __half* Ks = Qs + 128 * QS_STR;          // [2][64][KS_STR]
    __half* Vs = Ks + 2 * 64 * KS_STR;       // [2][256][VS_STR] ([d][key])

    const int tid = threadIdx.x;
    const int lane = tid & 31;
    const int g = lane >> 2, t = lane & 3;
    const int w = tid >> 5;
    const int rb = w * 16;

    const int a_row = ((lane >> 3) & 1) * 8 + (lane & 7);
    const int a_kh  = (lane >> 4) * 8;
    const int b_row = ((lane >> 4) & 1) * 8 + (lane & 7);
    const int b_kh  = ((lane >> 3) & 1) * 8;

    const int qt = (int)gridDim.y - 1 - (int)blockIdx.y;   // heavy first
    const int b  = blockIdx.x >> 4;
    const int h  = blockIdx.x & 15;
    const int kvh = h >> 3;
    const int q0 = qt * 128;

    const __half* Kp  = g_kr + ((size_t)b * NKVH + kvh) * SS * DH;
    const __half* VpT = g_vr + (size_t)(kvh * DH) * MM + (size_t)b * SS;

    auto issueKV = [&](int kt, int st) {
        const __half* Kt = Kp + (size_t)(kt * 64) * DH;
        __half* Kd = Ks + st * 64 * KS_STR;
        __half* Vd = Vs + st * 256 * VS_STR;
#pragma unroll
        for (int it = 0; it < 8; it++) {
            const int idx = tid + it * 256;
            const int key = idx >> 5;
            const int col = (idx & 31) * 8;
            cp16(Kd + key * KS_STR + col, Kt + (size_t)key * DH + col);
            const int dl = idx >> 3;
            const int kc = (idx & 7) * 8;
            cp16(Vd + dl * VS_STR + kc, VpT + (size_t)dl * MM + kt * 64 + kc);
        }
        cp_commit();
    };

    const int ktmax = 2 * qt + 1;
    issueKV(0, 0);
    issueKV(1, 1);

    // ---- inline Q prep: per-warp rows rb..rb+15, rms+rope+scale -> Qs ----
    {
        const int d0 = lane * 8;
        float wv[8];
        *(float4*)(wv)     = *(const float4*)(qw + d0);
        *(float4*)(wv + 4) = *(const float4*)(qw + d0 + 4);
        const __half* QGp = g_qg + ((size_t)(b * SS + q0 + rb)) * QGN + h * 512 + d0;
#pragma unroll
        for (int it = 0; it < 16; it++) {
            uint4 raw = *(const uint4*)(QGp + (size_t)it * QGN);
            const __half* hx = (const __half*)&raw;
            float x[8];
#pragma unroll
            for (int j = 0; j < 8; j++) x[j] = __half2float(hx[j]);
            float ss = 0.f;
#pragma unroll
            for (int j = 0; j < 8; j++) ss += x[j] * x[j];
#pragma unroll
            for (int o = 16; o; o >>= 1) ss += __shfl_xor_sync(0xffffffffu, ss, o);
            const float rsn = rsqrtf(ss * (1.0f / 256.0f) + 1e-6f);
            float xn[8];
#pragma unroll
            for (int j = 0; j < 8; j++) xn[j] = x[j] * rsn * (1.0f + wv[j]);
            float rot[8];
#pragma unroll
            for (int j = 0; j < 8; j++) rot[j] = __shfl_xor_sync(0xffffffffu, xn[j], 4);
            if (lane < 8) {
                const size_t token = (size_t)b * SS + q0 + rb + it;
                float cs[8], sn[8];
                *(float4*)(cs)     = *(const float4*)(cosp + token * ROT + d0);
                *(float4*)(cs + 4) = *(const float4*)(cosp + token * ROT + d0 + 4);
                *(float4*)(sn)     = *(const float4*)(sinp + token * ROT + d0);
                *(float4*)(sn + 4) = *(const float4*)(sinp + token * ROT + d0 + 4);
#pragma unroll
                for (int j = 0; j < 8; j++) {
                    float rr = (lane & 4) ? rot[j] : -rot[j];
                    xn[j] = xn[j] * cs[j] + rr * sn[j];
                }
            }
            __half2 hq[4];
#pragma unroll
            for (int j = 0; j < 4; j++)
                hq[j] = __floats2half2_rn(xn[2*j] * 0.0625f, xn[2*j+1] * 0.0625f);
            *(uint4*)&Qs[(rb + it) * QS_STR + d0] = *(uint4*)hq;
        }
        __syncwarp();
    }

    float o[32][4];
    float m[2], l[2];
#pragma unroll
    for (int cc = 0; cc < 32; cc++)
#pragma unroll
        for (int r = 0; r < 4; r++) o[cc][r] = 0.f;
    m[0] = m[1] = -1e30f; l[0] = l[1] = 0.f;

    for (int kt = 0; kt <= ktmax; kt++) {
        const int st = kt & 1;
        if (kt + 1 <= ktmax) asm volatile("cp.async.wait_group 1;\n");
        else                 asm volatile("cp.async.wait_group 0;\n");
        __syncthreads();

        const bool active = (kt * 64 <= q0 + rb + 15);

        float s[8][4];
        if (active) {
            const __half* Kd = Ks + st * 64 * KS_STR;
            const __half* Vd = Vs + st * 256 * VS_STR;
#pragma unroll
            for (int nt = 0; nt < 8; nt++)
#pragma unroll
                for (int r = 0; r < 4; r++) s[nt][r] = 0.f;

#pragma unroll
            for (int kk = 0; kk < 256; kk += 16) {
                unsigned a[4], bq[4][4];
                ldsm4(a, Qs + (rb + a_row) * QS_STR + kk + a_kh);
#pragma unroll
                for (int p = 0; p < 4; p++)
                    ldsm4(bq[p], Kd + (p * 16 + b_row) * KS_STR + kk + b_kh);
#pragma unroll
                for (int nt = 0; nt < 8; nt++)
                    mma_f16(s[nt], a, &bq[nt >> 1][(nt & 1) * 2]);
            }

            if (kt >= 2 * qt) {
#pragma unroll
                for (int nt = 0; nt < 8; nt++)
#pragma unroll
                    for (int r = 0; r < 4; r++) {
                        const int row = q0 + rb + (r >> 1) * 8 + g;
                        const int col = kt * 64 + nt * 8 + 2 * t + (r & 1);
                        if (col > row) s[nt][r] = -1e30f;
                    }
            }

            float al[2];
            bool changed[2];
#pragma unroll
            for (int hh = 0; hh < 2; hh++) {
                float v = -1e30f;
#pragma unroll
                for (int nt = 0; nt < 8; nt++)
                    v = fmaxf(v, fmaxf(s[nt][hh * 2], s[nt][hh * 2 + 1]));
                v = fmaxf(v, __shfl_xor_sync(0xffffffffu, v, 1));
                v = fmaxf(v, __shfl_xor_sync(0xffffffffu, v, 2));
                float mn = fmaxf(m[hh], v);
                al[hh] = __expf(m[hh] - mn);
                changed[hh] = __any_sync(0xffffffffu, mn != m[hh]);
                m[hh] = mn;
                float rs = 0.f;
#pragma unroll
                for (int nt = 0; nt < 8; nt++) {
                    float p0 = __expf(s[nt][hh * 2]     - mn);
                    float p1 = __expf(s[nt][hh * 2 + 1] - mn);
                    s[nt][hh * 2] = p0; s[nt][hh * 2 + 1] = p1;
                    rs += p0 + p1;
                }
                rs += __shfl_xor_sync(0xffffffffu, rs, 1);
                rs += __shfl_xor_sync(0xffffffffu, rs, 2);
                l[hh] = l[hh] * al[hh] + rs;
            }
            if (changed[0]) {
#pragma unroll
                for (int cc = 0; cc < 32; cc++) {
                    o[cc][0] *= al[0]; o[cc][1] *= al[0];
                }
            }
            if (changed[1]) {
#pragma unroll
                for (int cc = 0; cc < 32; cc++) {
                    o[cc][2] *= al[1]; o[cc][3] *= al[1];
                }
            }

#pragma unroll
            for (int kk4 = 0; kk4 < 4; kk4++) {
                unsigned pa[4];
                pa[0] = pack_h2(s[2*kk4][0],   s[2*kk4][1]);
                pa[1] = pack_h2(s[2*kk4][2],   s[2*kk4][3]);
                pa[2] = pack_h2(s[2*kk4+1][0], s[2*kk4+1][1]);
                pa[3] = pack_h2(s[2*kk4+1][2], s[2*kk4+1][3]);
#pragma unroll
                for (int half = 0; half < 2; half++) {
                    unsigned bv[8][4];
#pragma unroll
                    for (int p = 0; p < 8; p++)
                        ldsm4(bv[p], Vd + (half * 128 + p * 16 + b_row) * VS_STR + kk4 * 16 + b_kh);
#pragma unroll
                    for (int nt = 0; nt < 16; nt++)
                        mma_f16(o[half * 16 + nt], pa, &bv[nt >> 1][(nt & 1) * 2]);
                }
            }
        }

        __syncthreads();
        if (kt + 2 <= ktmax) issueKV(kt + 2, st);
    }

    // ---- epilogue: /l, * sigmoid(gate) ----
#pragma unroll
    for (int hh = 0; hh < 2; hh++) {
        const int row = q0 + rb + hh * 8 + g;
        const size_t token = (size_t)b * SS + row;
        const float inv = 1.f / l[hh];
#pragma unroll
        for (int cc = 0; cc < 32; cc++) {
            const int col = cc * 8 + 2 * t;
            __half2 gt2 = *(const __half2*)(g_qg + token * QGN + h * 512 + 256 + col);
            float2 gt = __half22float2(gt2);
            float ox = o[cc][hh * 2]     * inv / (1.f + __expf(-gt.x));
            float oy = o[cc][hh * 2 + 1] * inv / (1.f + __expf(-gt.y));
            *(__half2*)(g_attn + token * ODIM + h * 256 + col) =
                __floats2half2_rn(ox, oy);
        }
    }
}

// ---------------------------------------------------------------------------
extern "C" void kernel_launch(void* const* d_in, const int* in_sizes, int n_in,
                              void* d_out, int out_size)
{
    (void)in_sizes; (void)n_in; (void)out_size;
    const float* hs   = (const float*)d_in[0];
    const float* cosp = (const float*)d_in[1];
    const float* sinp = (const float*)d_in[2];
    const float* Wq   = (const float*)d_in[3];
    const float* Wk   = (const float*)d_in[4];
    const float* Wv   = (const float*)d_in[5];
    const float* Wo   = (const float*)d_in[6];
    const float* qw   = (const float*)d_in[7];
    const float* kw   = (const float*)d_in[8];
    float* out = (float*)d_out;

    // 0) Prep (single launch)
    prep_kernel<<<NB_PREP, 256>>>(hs, Wq, Wk, Wv, Wo);

    // 1) QG + K + V^T projections (one 1D launch)
    cudaFuncSetAttribute(hgemm_qkv_kernel, cudaFuncAttributeMaxDynamicSharedMemorySize, TG_SMEM);
    hgemm_qkv_kernel<<<2304, 256, TG_SMEM>>>();

    // 2) K RMSNorm + RoPE only (Q handled inside flash)
    k_post_kernel<<<MM * 2 / 8, 256>>>(cosp, sinp, kw);

    // 3) Flash attention + gate (inline Q prep)
    cudaFuncSetAttribute(flash_kernel, cudaFuncAttributeMaxDynamicSharedMemorySize, FL_SMEM);
    flash_kernel<<<dim3(BB * NH, SS / 128), 256, FL_SMEM>>>(cosp, sinp, qw);

    // 4) Output projection (fp32 out)
    cudaFuncSetAttribute(hgemm_o_kernel, cudaFuncAttributeMaxDynamicSharedMemorySize, TG_SMEM);
    hgemm_o_kernel<<<dim3(HID / 128, MM / 128), 256, TG_SMEM>>>(out);
}

// round 17
// speedup vs baseline: 1.0117x; 1.0117x over previous
#include <cuda_runtime.h>
#include <cuda_fp16.h>
#include <math.h>

// Problem constants
#define BB 2
#define SS 2048
#define HID 2048
#define NH 16
#define NKVH 2
#define DH 256
#define ROT 64
#define MM (BB*SS)          // 4096 tokens
#define QGN (NH*DH*2)       // 8192
#define KVN (NKVH*DH)       // 512
#define ODIM (NH*DH)        // 4096

// Scratch (device globals)
__device__ __half g_hs  [(size_t)MM * HID];
__device__ __half g_wqt [(size_t)QGN * HID];
__device__ __half g_wkvt[(size_t)(2*KVN) * HID];     // [Wk^T ; Wv^T]
__device__ __half g_wot [(size_t)HID * ODIM];
__device__ __half g_qg  [(size_t)MM * QGN];          // fp16 (q | gate)
__device__ __half g_kv  [(size_t)MM * KVN];          // fp16, K only
__device__ __half g_q   [(size_t)BB * NH  * SS * DH];
__device__ __half g_kr  [(size_t)BB * NKVH * SS * DH];
__device__ __half g_vr  [(size_t)KVN * MM];          // [kvh*256+d][b*2048+s]
__device__ __half g_attn[(size_t)MM * ODIM];

// ---------------- device helpers ----------------
__device__ __forceinline__ unsigned smem_u32(const void* p) {
    unsigned a;
    asm("{ .reg .u64 t; cvta.to.shared.u64 t, %1; cvt.u32.u64 %0, t; }" : "=r"(a) : "l"(p));
    return a;
}
__device__ __forceinline__ void mma_f16(float c[4], const unsigned a[4], const unsigned* b) {
    asm volatile(
        "mma.sync.aligned.m16n8k16.row.col.f32.f16.f16.f32 "
        "{%0,%1,%2,%3}, {%4,%5,%6,%7}, {%8,%9}, {%0,%1,%2,%3};\n"
        : "+f"(c[0]), "+f"(c[1]), "+f"(c[2]), "+f"(c[3])
        : "r"(a[0]), "r"(a[1]), "r"(a[2]), "r"(a[3]), "r"(b[0]), "r"(b[1]));
}
__device__ __forceinline__ void ldsm4(unsigned r[4], const __half* p) {
    unsigned a = smem_u32(p);
    asm volatile("ldmatrix.sync.aligned.m8n8.x4.shared.b16 {%0,%1,%2,%3}, [%4];\n"
                 : "=r"(r[0]), "=r"(r[1]), "=r"(r[2]), "=r"(r[3]) : "r"(a));
}
__device__ __forceinline__ void cp16(void* dst, const void* src) {
    unsigned d = (unsigned)__cvta_generic_to_shared(dst);
    asm volatile("cp.async.cg.shared.global [%0], [%1], 16;\n" :: "r"(d), "l"(src));
}
__device__ __forceinline__ void cp_commit() { asm volatile("cp.async.commit_group;\n"); }
__device__ __forceinline__ unsigned pack_h2(float a, float b) {
    __half2 h = __floats2half2_rn(a, b);
    return *(unsigned*)&h;
}

// ---------------------------------------------------------------------------
// Merged prep kernel
// ---------------------------------------------------------------------------
#define NB_HS 1024
#define NB_WQ ((QGN/32)*(HID/32))   // 16384
#define NB_WK ((KVN/32)*(HID/32))   // 1024
#define NB_WO ((HID/32)*(ODIM/32))  // 8192
#define NB_PREP (NB_HS + NB_WQ + 2*NB_WK + NB_WO)

__device__ __forceinline__ void tr_tile(
    float (*t)[33], const float* __restrict__ src, __half* __restrict__ dst,
    int R, int C, int bx, int by, int tid)
{
    const int tx = tid & 31, ty = tid >> 5;
    const int x = bx * 32 + tx;
    const int y0 = by * 32;
#pragma unroll
    for (int i = 0; i < 4; i++)
        t[ty + i * 8][tx] = src[(size_t)(y0 + ty + i * 8) * C + x];
    __syncthreads();
    const int nx = by * 32 + tx;
    const int ny0 = bx * 32;
#pragma unroll
    for (int i = 0; i < 4; i++)
        dst[(size_t)(ny0 + ty + i * 8) * R + nx] = __float2half(t[tx][ty + i * 8]);
}

__global__ __launch_bounds__(256) void prep_kernel(
    const float* __restrict__ hs,
    const float* __restrict__ Wq, const float* __restrict__ Wk,
    const float* __restrict__ Wv, const float* __restrict__ Wo)
{
    __shared__ float t[32][33];
    const int tid = threadIdx.x;
    int id = blockIdx.x;

    if (id < NB_HS) {
        const int n8 = MM * HID / 8;
        for (int i = id * 256 + tid; i < n8; i += NB_HS * 256) {
            float4 v0 = ((const float4*)hs)[i * 2];
            float4 v1 = ((const float4*)hs)[i * 2 + 1];
            __half2 h[4];
            h[0] = __floats2half2_rn(v0.x, v0.y);
            h[1] = __floats2half2_rn(v0.z, v0.w);
            h[2] = __floats2half2_rn(v1.x, v1.y);
            h[3] = __floats2half2_rn(v1.z, v1.w);
            ((uint4*)g_hs)[i] = *(uint4*)h;
        }
        return;
    }
    id -= NB_HS;
    if (id < NB_WQ) { tr_tile(t, Wq, g_wqt, HID, QGN, id % (QGN/32), id / (QGN/32), tid); return; }
    id -= NB_WQ;
    if (id < NB_WK) { tr_tile(t, Wk, g_wkvt, HID, KVN, id % (KVN/32), id / (KVN/32), tid); return; }
    id -= NB_WK;
    if (id < NB_WK) { tr_tile(t, Wv, g_wkvt + (size_t)KVN * HID, HID, KVN, id % (KVN/32), id / (KVN/32), tid); return; }
    id -= NB_WK;
    tr_tile(t, Wo, g_wot, ODIM, HID, id % (HID/32), id / (HID/32), tid);
}

// ---------------------------------------------------------------------------
// fp16 GEMM config: CTA 128x128, BK=32, 3-stage, 8 warps (4x2), warp 32x64.
// ---------------------------------------------------------------------------
#define GS_STR 40
#define TG_SMEM ((3*128*GS_STR + 3*128*GS_STR) * (int)sizeof(__half))

__global__ __launch_bounds__(256, 2) void hgemm_qkv_kernel()
{
    extern __shared__ __half hsm[];
    __half* As = hsm;
    __half* Bs = hsm + 3 * 128 * GS_STR;

    const int tid = threadIdx.x;
    int cid = blockIdx.x;
    const __half *A, *Bt; __half* C; int N, bx, by;
    if (cid < 2048)      { A = g_hs; Bt = g_wqt; C = g_qg; N = QGN; bx = cid & 63; by = cid >> 6; }
    else if (cid < 2176) { cid -= 2048; A = g_hs; Bt = g_wkvt; C = g_kv; N = KVN; bx = cid & 3; by = cid >> 2; }
    else                 { cid -= 2176; A = g_wkvt + (size_t)KVN * HID; Bt = g_hs; C = g_vr; N = MM; bx = cid & 31; by = cid >> 5; }

    const int lane = tid & 31;
    const int g = lane >> 2, t = lane & 3;
    const int wid = tid >> 5;
    const int m0 = (wid >> 1) * 32;
    const int n0 = (wid & 1) * 64;

    const int a_row = ((lane >> 3) & 1) * 8 + (lane & 7);
    const int a_kh  = (lane >> 4) * 8;
    const int b_row = ((lane >> 4) & 1) * 8 + (lane & 7);
    const int b_kh  = ((lane >> 3) & 1) * 8;

    const int nk = HID >> 5;

    auto issue = [&](int st, int k0) {
        __half* Ad = As + (size_t)st * 128 * GS_STR;
        __half* Bd = Bs + (size_t)st * 128 * GS_STR;
#pragma unroll
        for (int it = 0; it < 2; it++) {
            int idx = tid + it * 256;
            int row = idx >> 2;
            int ch  = (idx & 3) * 8;
            cp16(Ad + row * GS_STR + ch, A + (size_t)(by * 128 + row) * HID + k0 + ch);
            cp16(Bd + row * GS_STR + ch, Bt + (size_t)(bx * 128 + row) * HID + k0 + ch);
        }
        cp_commit();
    };

    issue(0, 0); issue(1, 32); issue(2, 64);

    float acc[2][8][4];
#pragma unroll
    for (int mt = 0; mt < 2; mt++)
#pragma unroll
        for (int nt = 0; nt < 8; nt++)
#pragma unroll
            for (int r = 0; r < 4; r++) acc[mt][nt][r] = 0.f;

    for (int i = 0; i < nk; i++) {
        const int st = i % 3;
        __half* Ad = As + (size_t)st * 128 * GS_STR;
        __half* Bd = Bs + (size_t)st * 128 * GS_STR;
        if (i + 2 < nk)      asm volatile("cp.async.wait_group 2;\n");
        else if (i + 1 < nk) asm volatile("cp.async.wait_group 1;\n");
        else                 asm volatile("cp.async.wait_group 0;\n");
        __syncthreads();

#pragma unroll
        for (int kk = 0; kk < 32; kk += 16) {
            unsigned a[2][4], bfr[4][4];
#pragma unroll
            for (int mt = 0; mt < 2; mt++)
                ldsm4(a[mt], Ad + (m0 + mt * 16 + a_row) * GS_STR + kk + a_kh);
#pragma unroll
            for (int p = 0; p < 4; p++)
                ldsm4(bfr[p], Bd + (n0 + p * 16 + b_row) * GS_STR + kk + b_kh);
#pragma unroll
            for (int mt = 0; mt < 2; mt++)
#pragma unroll
                for (int nt = 0; nt < 8; nt++)
                    mma_f16(acc[mt][nt], a[mt], &bfr[nt >> 1][(nt & 1) * 2]);
        }
        __syncthreads();
        if (i + 3 < nk) issue(st, (i + 3) * 32);
    }

#pragma unroll
    for (int mt = 0; mt < 2; mt++) {
        const int r = by * 128 + m0 + mt * 16 + g;
#pragma unroll
        for (int nt = 0; nt < 8; nt++) {
            const int c = bx * 128 + n0 + nt * 8 + 2 * t;
            *(__half2*)(C + (size_t)r * N + c) =
                __floats2half2_rn(acc[mt][nt][0], acc[mt][nt][1]);
            *(__half2*)(C + (size_t)(r + 8) * N + c) =
                __floats2half2_rn(acc[mt][nt][2], acc[mt][nt][3]);
        }
    }
}

__global__ __launch_bounds__(256, 2) void hgemm_o_kernel(float* __restrict__ out)
{
    extern __shared__ __half hsm[];
    __half* As = hsm;
    __half* Bs = hsm + 3 * 128 * GS_STR;

    const int tid = threadIdx.x;
    const int bx = blockIdx.x, by = blockIdx.y;
    const __half* A  = g_attn;
    const __half* Bt = g_wot;
    const int N = HID;

    const int lane = tid & 31;
    const int g = lane >> 2, t = lane & 3;
    const int wid = tid >> 5;
    const int m0 = (wid >> 1) * 32;
    const int n0 = (wid & 1) * 64;

    const int a_row = ((lane >> 3) & 1) * 8 + (lane & 7);
    const int a_kh  = (lane >> 4) * 8;
    const int b_row = ((lane >> 4) & 1) * 8 + (lane & 7);
    const int b_kh  = ((lane >> 3) & 1) * 8;

    const int nk = ODIM >> 5;

    auto issue = [&](int st, int k0) {
        __half* Ad = As + (size_t)st * 128 * GS_STR;
        __half* Bd = Bs + (size_t)st * 128 * GS_STR;
#pragma unroll
        for (int it = 0; it < 2; it++) {
            int idx = tid + it * 256;
            int row = idx >> 2;
            int ch  = (idx & 3) * 8;
            cp16(Ad + row * GS_STR + ch, A + (size_t)(by * 128 + row) * ODIM + k0 + ch);
            cp16(Bd + row * GS_STR + ch, Bt + (size_t)(bx * 128 + row) * ODIM + k0 + ch);
        }
        cp_commit();
    };

    issue(0, 0); issue(1, 32); issue(2, 64);

    float acc[2][8][4];
#pragma unroll
    for (int mt = 0; mt < 2; mt++)
#pragma unroll
        for (int nt = 0; nt < 8; nt++)
#pragma unroll
            for (int r = 0; r < 4; r++) acc[mt][nt][r] = 0.f;

    for (int i = 0; i < nk; i++) {
        const int st = i % 3;
        __half* Ad = As + (size_t)st * 128 * GS_STR;
        __half* Bd = Bs + (size_t)st * 128 * GS_STR;
        if (i + 2 < nk)      asm volatile("cp.async.wait_group 2;\n");
        else if (i + 1 < nk) asm volatile("cp.async.wait_group 1;\n");
        else                 asm volatile("cp.async.wait_group 0;\n");
        __syncthreads();

#pragma unroll
        for (int kk = 0; kk < 32; kk += 16) {
            unsigned a[2][4], bfr[4][4];
#pragma unroll
            for (int mt = 0; mt < 2; mt++)
                ldsm4(a[mt], Ad + (m0 + mt * 16 + a_row) * GS_STR + kk + a_kh);
#pragma unroll
            for (int p = 0; p < 4; p++)
                ldsm4(bfr[p], Bd + (n0 + p * 16 + b_row) * GS_STR + kk + b_kh);
#pragma unroll
            for (int mt = 0; mt < 2; mt++)
#pragma unroll
                for (int nt = 0; nt < 8; nt++)
                    mma_f16(acc[mt][nt], a[mt], &bfr[nt >> 1][(nt & 1) * 2]);
        }
        __syncthreads();
        if (i + 3 < nk) issue(st, (i + 3) * 32);
    }

#pragma unroll
    for (int mt = 0; mt < 2; mt++) {
        const int r = by * 128 + m0 + mt * 16 + g;
#pragma unroll
        for (int nt = 0; nt < 8; nt++) {
            const int c = bx * 128 + n0 + nt * 8 + 2 * t;
            *(float2*)(out + (size_t)r * N + c)       = make_float2(acc[mt][nt][0], acc[mt][nt][1]);
            *(float2*)(out + (size_t)(r + 8) * N + c) = make_float2(acc[mt][nt][2], acc[mt][nt][3]);
        }
    }
}

// ---------------------------------------------------------------------------
// Post-process: one WARP per (token, unit); 18 units (16 Q + 2 K).
// ---------------------------------------------------------------------------
__global__ __launch_bounds__(256) void qkv_post_kernel(
    const float* __restrict__ cosp, const float* __restrict__ sinp,
    const float* __restrict__ qw, const float* __restrict__ kw)
{
    const int wi = blockIdx.x * 8 + (threadIdx.x >> 5);
    const int lane = threadIdx.x & 31;
    const int token = wi / 18;
    const int unit  = wi % 18;
    const int b = token >> 11;
    const int s = token & 2047;
    const int d0 = lane * 8;

    const __half* src;
    const float* w;
    if (unit < 16) { src = g_qg + (size_t)token * QGN + unit * 512 + d0; w = qw + d0; }
    else           { src = g_kv + (size_t)token * KVN + (unit - 16) * 256 + d0; w = kw + d0; }

    uint4 raw = *(const uint4*)src;
    const __half* hx = (const __half*)&raw;
    float x[8];
#pragma unroll
    for (int j = 0; j < 8; j++) x[j] = __half2float(hx[j]);

    float ss = 0.f;
#pragma unroll
    for (int j = 0; j < 8; j++) ss += x[j] * x[j];
#pragma unroll
    for (int o = 16; o; o >>= 1) ss += __shfl_xor_sync(0xffffffffu, ss, o);
    const float rsn = rsqrtf(ss * (1.0f / 256.0f) + 1e-6f);

    float xn[8];
#pragma unroll
    for (int j = 0; j < 8; j++) xn[j] = x[j] * rsn * (1.0f + w[j]);

    float rot[8];
#pragma unroll
    for (int j = 0; j < 8; j++) rot[j] = __shfl_xor_sync(0xffffffffu, xn[j], 4);
    if (lane < 8) {
        float cs[8], sn[8];
        *(float4*)(cs)     = *(const float4*)(cosp + (size_t)token * ROT + d0);
        *(float4*)(cs + 4) = *(const float4*)(cosp + (size_t)token * ROT + d0 + 4);
        *(float4*)(sn)     = *(const float4*)(sinp + (size_t)token * ROT + d0);
        *(float4*)(sn + 4) = *(const float4*)(sinp + (size_t)token * ROT + d0 + 4);
#pragma unroll
        for (int j = 0; j < 8; j++) {
            float rr = (lane & 4) ? rot[j] : -rot[j];
            xn[j] = xn[j] * cs[j] + rr * sn[j];
        }
    }

    __half2 h[4];
    if (unit < 16) {
#pragma unroll
        for (int j = 0; j < 4; j++)
            h[j] = __floats2half2_rn(xn[2*j] * 0.0625f, xn[2*j+1] * 0.0625f);
        *(uint4*)(g_q + (((size_t)b * NH + unit) * SS + s) * DH + d0) = *(uint4*)h;
    } else {
#pragma unroll
        for (int j = 0; j < 4; j++)
            h[j] = __floats2half2_rn(xn[2*j], xn[2*j+1]);
        *(uint4*)(g_kr + (((size_t)b * NKVH + (unit - 16)) * SS + s) * DH + d0) = *(uint4*)h;
    }
}

// ---------------------------------------------------------------------------
// Flash attention v8 + rescale-skip vote: warp-autonomous, register-resident
// P, K+V double-buffered, heavy q-tiles first, masked-warp skip.
// ---------------------------------------------------------------------------
#define QS_STR 264
#define KS_STR 264
#define VS_STR 72
#define FL_SMEM ((128*QS_STR + 2*64*KS_STR + 2*256*VS_STR) * 2)

__global__ __launch_bounds__(256, 1) void flash_kernel()
{
    extern __shared__ __half smh[];
    __half* Qs = smh;                        // [128][QS_STR]
    __half* Ks = Qs + 128 * QS_STR;          // [2][64][KS_STR]
    __half* Vs = Ks + 2 * 64 * KS_STR;       // [2][256][VS_STR] ([d][key])

    const int tid = threadIdx.x;
    const int lane = tid & 31;
    const int g = lane >> 2, t = lane & 3;
    const int w = tid >> 5;
    const int rb = w * 16;

    const int a_row = ((lane >> 3) & 1) * 8 + (lane & 7);
    const int a_kh  = (lane >> 4) * 8;
    const int b_row = ((lane >> 4) & 1) * 8 + (lane & 7);
    const int b_kh  = ((lane >> 3) & 1) * 8;

    const int qt = (int)gridDim.y - 1 - (int)blockIdx.y;   // heavy first
    const int b  = blockIdx.x >> 4;
    const int h  = blockIdx.x & 15;
    const int kvh = h >> 3;
    const int q0 = qt * 128;

    const __half* Qp  = g_q  + (((size_t)b * NH + h) * SS + q0) * DH;
    const __half* Kp  = g_kr + ((size_t)b * NKVH + kvh) * SS * DH;
    const __half* VpT = g_vr + (size_t)(kvh * DH) * MM + (size_t)b * SS;

    auto issueKV = [&](int kt, int st) {
        const __half* Kt = Kp + (size_t)(kt * 64) * DH;
        __half* Kd = Ks + st * 64 * KS_STR;
        __half* Vd = Vs + st * 256 * VS_STR;
#pragma unroll
        for (int it = 0; it < 8; it++) {
            const int idx = tid + it * 256;
            const int key = idx >> 5;
            const int col = (idx & 31) * 8;
            cp16(Kd + key * KS_STR + col, Kt + (size_t)key * DH + col);
            const int dl = idx >> 3;
            const int kc = (idx & 7) * 8;
            cp16(Vd + dl * VS_STR + kc, VpT + (size_t)dl * MM + kt * 64 + kc);
        }
        cp_commit();
    };

    // Q resident
#pragma unroll
    for (int it = 0; it < 16; it++) {
        const int idx = tid + it * 256;
        const int r = idx >> 5;
        const int c = (idx & 31) * 8;
        *(uint4*)&Qs[r * QS_STR + c] = *(const uint4*)(Qp + (size_t)r * DH + c);
    }

    float o[32][4];
    float m[2], l[2];
#pragma unroll
    for (int cc = 0; cc < 32; cc++)
#pragma unroll
        for (int r = 0; r < 4; r++) o[cc][r] = 0.f;
    m[0] = m[1] = -1e30f; l[0] = l[1] = 0.f;

    const int ktmax = 2 * qt + 1;

    issueKV(0, 0);
    issueKV(1, 1);

    for (int kt = 0; kt <= ktmax; kt++) {
        const int st = kt & 1;
        if (kt + 1 <= ktmax) asm volatile("cp.async.wait_group 1;\n");
        else                 asm volatile("cp.async.wait_group 0;\n");
        __syncthreads();

        const bool active = (kt * 64 <= q0 + rb + 15);

        float s[8][4];
        if (active) {
            const __half* Kd = Ks + st * 64 * KS_STR;
            const __half* Vd = Vs + st * 256 * VS_STR;
#pragma unroll
            for (int nt = 0; nt < 8; nt++)
#pragma unroll
                for (int r = 0; r < 4; r++) s[nt][r] = 0.f;

#pragma unroll
            for (int kk = 0; kk < 256; kk += 16) {
                unsigned a[4], bq[4][4];
                ldsm4(a, Qs + (rb + a_row) * QS_STR + kk + a_kh);
#pragma unroll
                for (int p = 0; p < 4; p++)
                    ldsm4(bq[p], Kd + (p * 16 + b_row) * KS_STR + kk + b_kh);
#pragma unroll
                for (int nt = 0; nt < 8; nt++)
                    mma_f16(s[nt], a, &bq[nt >> 1][(nt & 1) * 2]);
            }

            if (kt >= 2 * qt) {
#pragma unroll
                for (int nt = 0; nt < 8; nt++)
#pragma unroll
                    for (int r = 0; r < 4; r++) {
                        const int row = q0 + rb + (r >> 1) * 8 + g;
                        const int col = kt * 64 + nt * 8 + 2 * t + (r & 1);
                        if (col > row) s[nt][r] = -1e30f;
                    }
            }

            float al[2];
            bool changed[2];
#pragma unroll
            for (int hh = 0; hh < 2; hh++) {
                float v = -1e30f;
#pragma unroll
                for (int nt = 0; nt < 8; nt++)
                    v = fmaxf(v, fmaxf(s[nt][hh * 2], s[nt][hh * 2 + 1]));
                v = fmaxf(v, __shfl_xor_sync(0xffffffffu, v, 1));
                v = fmaxf(v, __shfl_xor_sync(0xffffffffu, v, 2));
                float mn = fmaxf(m[hh], v);
                al[hh] = __expf(m[hh] - mn);
                changed[hh] = __any_sync(0xffffffffu, mn != m[hh]);
                m[hh] = mn;
                float rs = 0.f;
#pragma unroll
                for (int nt = 0; nt < 8; nt++) {
                    float p0 = __expf(s[nt][hh * 2]     - mn);
                    float p1 = __expf(s[nt][hh * 2 + 1] - mn);
                    s[nt][hh * 2] = p0; s[nt][hh * 2 + 1] = p1;
                    rs += p0 + p1;
                }
                rs += __shfl_xor_sync(0xffffffffu, rs, 1);
                rs += __shfl_xor_sync(0xffffffffu, rs, 2);
                l[hh] = l[hh] * al[hh] + rs;
            }
            if (changed[0]) {
#pragma unroll
                for (int cc = 0; cc < 32; cc++) {
                    o[cc][0] *= al[0]; o[cc][1] *= al[0];
                }
            }
            if (changed[1]) {
#pragma unroll
                for (int cc = 0; cc < 32; cc++) {
                    o[cc][2] *= al[1]; o[cc][3] *= al[1];
                }
            }

#pragma unroll
            for (int kk4 = 0; kk4 < 4; kk4++) {
                unsigned pa[4];
                pa[0] = pack_h2(s[2*kk4][0],   s[2*kk4][1]);
                pa[1] = pack_h2(s[2*kk4][2],   s[2*kk4][3]);
                pa[2] = pack_h2(s[2*kk4+1][0], s[2*kk4+1][1]);
                pa[3] = pack_h2(s[2*kk4+1][2], s[2*kk4+1][3]);
#pragma unroll
                for (int half = 0; half < 2; half++) {
                    unsigned bv[8][4];
#pragma unroll
                    for (int p = 0; p < 8; p++)
                        ldsm4(bv[p], Vd + (half * 128 + p * 16 + b_row) * VS_STR + kk4 * 16 + b_kh);
#pragma unroll
                    for (int nt = 0; nt < 16; nt++)
                        mma_f16(o[half * 16 + nt], pa, &bv[nt >> 1][(nt & 1) * 2]);
                }
            }
        }

        __syncthreads();
        if (kt + 2 <= ktmax) issueKV(kt + 2, st);
    }

    // ---- epilogue: /l, * sigmoid(gate) ----
#pragma unroll
    for (int hh = 0; hh < 2; hh++) {
        const int row = q0 + rb + hh * 8 + g;
        const size_t token = (size_t)b * SS + row;
        const float inv = 1.f / l[hh];
#pragma unroll
        for (int cc = 0; cc < 32; cc++) {
            const int col = cc * 8 + 2 * t;
            __half2 gt2 = *(const __half2*)(g_qg + token * QGN + h * 512 + 256 + col);
            float2 gt = __half22float2(gt2);
            float ox = o[cc][hh * 2]     * inv / (1.f + __expf(-gt.x));
            float oy = o[cc][hh * 2 + 1] * inv / (1.f + __expf(-gt.y));
            *(__half2*)(g_attn + token * ODIM + h * 256 + col) =
                __floats2half2_rn(ox, oy);
        }
    }
}

// ---------------------------------------------------------------------------
extern "C" void kernel_launch(void* const* d_in, const int* in_sizes, int n_in,
                              void* d_out, int out_size)
{
    (void)in_sizes; (void)n_in; (void)out_size;
    const float* hs   = (const float*)d_in[0];
    const float* cosp = (const float*)d_in[1];
    const float* sinp = (const float*)d_in[2];
    const float* Wq   = (const float*)d_in[3];
    const float* Wk   = (const float*)d_in[4];
    const float* Wv   = (const float*)d_in[5];
    const float* Wo   = (const float*)d_in[6];
    const float* qw   = (const float*)d_in[7];
    const float* kw   = (const float*)d_in[8];
    float* out = (float*)d_out;

    // 0) Prep (single launch)
    prep_kernel<<<NB_PREP, 256>>>(hs, Wq, Wk, Wv, Wo);

    // 1) QG + K + V^T projections (one 1D launch)
    cudaFuncSetAttribute(hgemm_qkv_kernel, cudaFuncAttributeMaxDynamicSharedMemorySize, TG_SMEM);
    hgemm_qkv_kernel<<<2304, 256, TG_SMEM>>>();

    // 2) RMSNorm + RoPE (Q + K)
    qkv_post_kernel<<<MM * 18 / 8, 256>>>(cosp, sinp, qw, kw);

    // 3) Flash attention + gate (rescale-skip vote)
    cudaFuncSetAttribute(flash_kernel, cudaFuncAttributeMaxDynamicSharedMemorySize, FL_SMEM);
    flash_kernel<<<dim3(BB * NH, SS / 128), 256, FL_SMEM>>>();

    // 4) Output projection (fp32 out)
    cudaFuncSetAttribute(hgemm_o_kernel, cudaFuncAttributeMaxDynamicSharedMemorySize, TG_SMEM);
    hgemm_o_kernel<<<dim3(HID / 128, MM / 128), 256, TG_SMEM>>>(out);
}